// round 4
// baseline (speedup 1.0000x reference)
#include <cuda_runtime.h>
#include <cstdint>

// Problem constants (from reference): SUPPORT=(16,16), N_NODES=100000, F=64, B=4096
#define BATCH_N    4096
#define SUP        16
#define FDIM       64
#define ROW_LEN    65          // 1 weight + 64 features
#define ROWS_PER_B 1088        // 2 * 16 * 34
#define GROUP_ROWS 34          // 2 + 2*16
#define N_GROUPS   (BATCH_N * 2 * SUP)   // 131072 warps
#define WARPS_PER_BLOCK 8
#define THREADS (WARPS_PER_BLOCK * 32)

__global__ __launch_bounds__(THREADS)
void gae_gather_kernel(const int*   __restrict__ node_ids,
                       const float* __restrict__ features,
                       const int*   __restrict__ in_sample,
                       const int*   __restrict__ out_sample,
                       const float* __restrict__ in_amnt,
                       const float* __restrict__ out_amnt,
                       float*       __restrict__ feat_out,
                       float*       __restrict__ w_out) {
    const int warp_in_block = threadIdx.x >> 5;
    const int lane = threadIdx.x & 31;
    const int g = blockIdx.x * WARPS_PER_BLOCK + warp_in_block;
    if (g >= N_GROUPS) return;

    const int b    = g >> 5;        // 32 groups per batch element
    const int rem  = g & 31;
    const int half = rem >> 4;      // 0 = in-branch at hop1, 1 = out-branch
    const int i    = rem & 15;      // first-hop neighbor index

    const int n = node_ids[b];
    const int*   s1 = half ? out_sample : in_sample;
    const float* a1 = half ? out_amnt  : in_amnt;
    const int   n1 = s1[n * SUP + i];
    const float w1 = a1[n * SUP + i];

    // Per-lane precompute of (node, scalar) for row r = lane (0..31).
    int   mA;  float sA;
    {
        const int r = lane;
        if (r == 0 || r == 17) { mA = n1; sA = w1; }
        else if (r <= 16)      { mA = in_sample [n1 * SUP + (r - 1)];
                                 sA = in_amnt   [n1 * SUP + (r - 1)]; }
        else                   { mA = out_sample[n1 * SUP + (r - 18)];
                                 sA = out_amnt  [n1 * SUP + (r - 18)]; }
    }
    // Rows 32,33 (j = 14,15 of the out-branch) on lanes 0,1.
    int mB = 0; float sB = 0.f;
    if (lane < 2) {
        mB = out_sample[n1 * SUP + (14 + lane)];
        sB = out_amnt  [n1 * SUP + (14 + lane)];
    }

    const size_t rowbase = (size_t)b * ROWS_PER_B + (size_t)half * 544 + (size_t)i * GROUP_ROWS;

    // Weight output: w1^2 for self-rows, w2*w1 otherwise.
    {
        const float wv = (lane == 0 || lane == 17) ? (w1 * w1) : (sA * w1);
        w_out[rowbase + lane] = wv;
        if (lane < 2) w_out[rowbase + 32 + lane] = sB * w1;
    }

    // Feature rows: broadcast (m, s) from the owning lane, copy 64 floats + scalar.
    #pragma unroll 2
    for (int rr = 0; rr < GROUP_ROWS; rr++) {
        int m; float s;
        if (rr < 32) {
            m = __shfl_sync(0xffffffffu, mA, rr);
            s = __shfl_sync(0xffffffffu, sA, rr);
        } else {
            m = __shfl_sync(0xffffffffu, mB, rr - 32);
            s = __shfl_sync(0xffffffffu, sB, rr - 32);
        }
        float* dst = feat_out + (rowbase + rr) * (size_t)ROW_LEN;
        const float* src = features + (size_t)m * FDIM;
        const float v0 = src[lane];
        const float v1 = src[lane + 32];
        if (lane == 0) dst[0] = s;
        dst[1 + lane]      = v0;
        dst[1 + lane + 32] = v1;
    }
}

extern "C" void kernel_launch(void* const* d_in, const int* in_sizes, int n_in,
                              void* d_out, int out_size) {
    const int*   node_ids = (const int*)  d_in[0];
    const float* features = (const float*)d_in[1];
    const int*   in_samp  = (const int*)  d_in[2];
    const int*   out_samp = (const int*)  d_in[3];
    const float* in_amnt  = (const float*)d_in[4];
    const float* out_amnt = (const float*)d_in[5];

    float* feat_out = (float*)d_out;
    float* w_out    = feat_out + (size_t)BATCH_N * ROWS_PER_B * ROW_LEN;

    const int blocks = N_GROUPS / WARPS_PER_BLOCK;   // 16384
    gae_gather_kernel<<<blocks, THREADS>>>(node_ids, features, in_samp, out_samp,
                                           in_amnt, out_amnt, feat_out, w_out);
}